// round 1
// baseline (speedup 1.0000x reference)
#include <cuda_runtime.h>

// ---------------- problem constants ----------------
constexpr int cB = 32768, cS = 5, cD = 512, cE = 256, cNH = 4, cDH = 64,
              cF = 2048, cL = 2, cC = 5;
constexpr int cBS = cB * cS;               // 163840 rows
constexpr int cZK = cS * cE;               // 1280, head input dim

// ---------------- scratch (device globals; no allocs) ----------------
__device__ float g_H [(size_t)cBS * cE];   // hidden state [BS,256]
__device__ float g_T [(size_t)cBS * cF];   // qkv [BS,768] / ff1 [BS,2048]
__device__ float g_O [(size_t)cBS * cE];   // attention output
__device__ float g_Cb[(size_t)cBS * cE];   // pre-LN gemm output
__device__ float g_Z1[(size_t)cB * 128];
__device__ float g_Z2[(size_t)cB * 64];

// ---------------- generic fp32 GEMM: C[m,n] = sum_k A[m,k]*W[n,k] + bias[n] ----------------
// Tiles: BM=BN=64, BK=16, 256 threads, 4x4 microtile. M%64==0, N%64==0, K%16==0 (all shapes here).
template<bool RELU>
__global__ __launch_bounds__(256) void gemm_bias(
    const float* __restrict__ A, const float* __restrict__ W,
    const float* __restrict__ bias, float* __restrict__ C,
    int M, int N, int K)
{
    __shared__ float As[16][68];
    __shared__ float Ws[16][68];
    const int t  = threadIdx.x;
    const int bm = blockIdx.y * 64, bn = blockIdx.x * 64;
    const int tm = (t >> 4) << 2;          // 0..60
    const int tn = (t & 15) << 2;          // 0..60
    const int lr = t >> 2;                 // 0..63
    const int lc = (t & 3) << 2;           // 0,4,8,12

    float acc[4][4] = {};
    const float* Ap = A + (size_t)(bm + lr) * K + lc;
    const float* Wp = W + (size_t)(bn + lr) * K + lc;

    for (int k0 = 0; k0 < K; k0 += 16) {
        float4 av = *(const float4*)(Ap + k0);
        float4 wv = *(const float4*)(Wp + k0);
        As[lc+0][lr]=av.x; As[lc+1][lr]=av.y; As[lc+2][lr]=av.z; As[lc+3][lr]=av.w;
        Ws[lc+0][lr]=wv.x; Ws[lc+1][lr]=wv.y; Ws[lc+2][lr]=wv.z; Ws[lc+3][lr]=wv.w;
        __syncthreads();
#pragma unroll
        for (int k = 0; k < 16; k++) {
            float4 a4 = *(const float4*)&As[k][tm];
            float4 w4 = *(const float4*)&Ws[k][tn];
            const float ar[4] = {a4.x, a4.y, a4.z, a4.w};
            const float wr[4] = {w4.x, w4.y, w4.z, w4.w};
#pragma unroll
            for (int r = 0; r < 4; r++)
#pragma unroll
                for (int c = 0; c < 4; c++)
                    acc[r][c] = fmaf(ar[r], wr[c], acc[r][c]);
        }
        __syncthreads();
    }

    float4 bv = *(const float4*)&bias[bn + tn];
    const float bb[4] = {bv.x, bv.y, bv.z, bv.w};
#pragma unroll
    for (int r = 0; r < 4; r++) {
        float4 o;
        float* op = (float*)&o;
#pragma unroll
        for (int c = 0; c < 4; c++) {
            float v = acc[r][c] + bb[c];
            if (RELU) v = fmaxf(v, 0.f);
            op[c] = v;
        }
        *(float4*)&C[(size_t)(bm + tm + r) * N + bn + tn] = o;
    }
}

// ---------------- embed: relu(x @ Wsel^T + bsel), Wsel per-row (gps if type==0 else ang) ----
// Dual-accumulate both experts; select per row in epilogue. M=BS, N=256, K=512.
__global__ __launch_bounds__(256) void embed_kernel(
    const float* __restrict__ X,
    const float* __restrict__ GW, const float* __restrict__ GB,
    const float* __restrict__ AW, const float* __restrict__ AB,
    const int*   __restrict__ ST, float* __restrict__ Hout)
{
    __shared__ float Xs[16][68];
    __shared__ float Gs[16][68];
    __shared__ float As[16][68];
    const int t  = threadIdx.x;
    const int bm = blockIdx.y * 64, bn = blockIdx.x * 64;
    const int tm = (t >> 4) << 2;
    const int tn = (t & 15) << 2;
    const int lr = t >> 2;
    const int lc = (t & 3) << 2;

    float accG[4][4] = {}, accA[4][4] = {};
    const float* Xp = X  + (size_t)(bm + lr) * cD + lc;
    const float* Gp = GW + (size_t)(bn + lr) * cD + lc;
    const float* Ap = AW + (size_t)(bn + lr) * cD + lc;

    for (int k0 = 0; k0 < cD; k0 += 16) {
        float4 xv = *(const float4*)(Xp + k0);
        float4 gv = *(const float4*)(Gp + k0);
        float4 av = *(const float4*)(Ap + k0);
        Xs[lc+0][lr]=xv.x; Xs[lc+1][lr]=xv.y; Xs[lc+2][lr]=xv.z; Xs[lc+3][lr]=xv.w;
        Gs[lc+0][lr]=gv.x; Gs[lc+1][lr]=gv.y; Gs[lc+2][lr]=gv.z; Gs[lc+3][lr]=gv.w;
        As[lc+0][lr]=av.x; As[lc+1][lr]=av.y; As[lc+2][lr]=av.z; As[lc+3][lr]=av.w;
        __syncthreads();
#pragma unroll
        for (int k = 0; k < 16; k++) {
            float4 x4 = *(const float4*)&Xs[k][tm];
            float4 g4 = *(const float4*)&Gs[k][tn];
            float4 a4 = *(const float4*)&As[k][tn];
            const float xr[4] = {x4.x, x4.y, x4.z, x4.w};
            const float gr[4] = {g4.x, g4.y, g4.z, g4.w};
            const float ar[4] = {a4.x, a4.y, a4.z, a4.w};
#pragma unroll
            for (int r = 0; r < 4; r++)
#pragma unroll
                for (int c = 0; c < 4; c++) {
                    accG[r][c] = fmaf(xr[r], gr[c], accG[r][c]);
                    accA[r][c] = fmaf(xr[r], ar[c], accA[r][c]);
                }
        }
        __syncthreads();
    }

    float4 gbv = *(const float4*)&GB[bn + tn];
    float4 abv = *(const float4*)&AB[bn + tn];
    const float gb[4] = {gbv.x, gbv.y, gbv.z, gbv.w};
    const float ab[4] = {abv.x, abv.y, abv.z, abv.w};
#pragma unroll
    for (int r = 0; r < 4; r++) {
        const int bs = bm + tm + r;
        const bool isg = (ST[bs] == 0);
        float4 o; float* op = (float*)&o;
#pragma unroll
        for (int c = 0; c < 4; c++) {
            float v = isg ? (accG[r][c] + gb[c]) : (accA[r][c] + ab[c]);
            op[c] = fmaxf(v, 0.f);
        }
        *(float4*)&Hout[(size_t)bs * cE + bn + tn] = o;
    }
}

// ---------------- attention: one warp per (batch, head) ----------------
// QKV layout [BS,768]: q=[0:256), k=[256:512), v=[512:768), head h -> cols h*64..h*64+63.
__global__ __launch_bounds__(256) void attn_kernel(
    const float* __restrict__ QKV, float* __restrict__ O)
{
    const int gwarp = (blockIdx.x * blockDim.x + threadIdx.x) >> 5;
    const int lane  = threadIdx.x & 31;
    if (gwarp >= cB * cNH) return;
    const int b = gwarp >> 2, h = gwarp & 3;

    const float* base = QKV + (size_t)b * cS * 768 + h * 64 + 2 * lane;
    float q[cS][2], kk[cS][2], vv[cS][2];
#pragma unroll
    for (int s = 0; s < cS; s++) {
        const float* r = base + s * 768;
        float2 qv = *(const float2*)(r);
        float2 kv = *(const float2*)(r + 256);
        float2 vw = *(const float2*)(r + 512);
        q [s][0] = qv.x; q [s][1] = qv.y;
        kk[s][0] = kv.x; kk[s][1] = kv.y;
        vv[s][0] = vw.x; vv[s][1] = vw.y;
    }

    float sc[cS][cS];
#pragma unroll
    for (int i = 0; i < cS; i++)
#pragma unroll
        for (int j = 0; j < cS; j++) {
            float p = q[i][0] * kk[j][0] + q[i][1] * kk[j][1];
#pragma unroll
            for (int o = 16; o > 0; o >>= 1) p += __shfl_xor_sync(0xFFFFFFFFu, p, o);
            sc[i][j] = p * 0.125f;   // 1/sqrt(64)
        }

#pragma unroll
    for (int i = 0; i < cS; i++) {
        float m = sc[i][0];
#pragma unroll
        for (int j = 1; j < cS; j++) m = fmaxf(m, sc[i][j]);
        float e[cS], s = 0.f;
#pragma unroll
        for (int j = 0; j < cS; j++) { e[j] = expf(sc[i][j] - m); s += e[j]; }
        const float inv = 1.f / s;
        float o0 = 0.f, o1 = 0.f;
#pragma unroll
        for (int j = 0; j < cS; j++) {
            const float a = e[j] * inv;
            o0 = fmaf(a, vv[j][0], o0);
            o1 = fmaf(a, vv[j][1], o1);
        }
        float2 ov = {o0, o1};
        *(float2*)&O[(size_t)(b * cS + i) * cE + h * 64 + 2 * lane] = ov;
    }
}

// ---------------- fused residual + layernorm: one warp per row of 256 ----------------
__global__ __launch_bounds__(256) void add_ln_kernel(
    const float* __restrict__ Hin, const float* __restrict__ Cin,
    const float* __restrict__ G, const float* __restrict__ Bv,
    float* __restrict__ Hout)
{
    const int row  = blockIdx.x * 8 + (threadIdx.x >> 5);
    const int lane = threadIdx.x & 31;
    const size_t rb = (size_t)row * cE;

    float v[8];
    float s = 0.f;
#pragma unroll
    for (int i = 0; i < 8; i++) {
        const int e = i * 32 + lane;
        v[i] = Hin[rb + e] + Cin[rb + e];
        s += v[i];
    }
#pragma unroll
    for (int o = 16; o > 0; o >>= 1) s += __shfl_xor_sync(0xFFFFFFFFu, s, o);
    const float mean = s * (1.f / cE);

    float vs = 0.f;
#pragma unroll
    for (int i = 0; i < 8; i++) { const float d = v[i] - mean; vs += d * d; }
#pragma unroll
    for (int o = 16; o > 0; o >>= 1) vs += __shfl_xor_sync(0xFFFFFFFFu, vs, o);
    const float rs = rsqrtf(vs * (1.f / cE) + 1e-5f);

#pragma unroll
    for (int i = 0; i < 8; i++) {
        const int e = i * 32 + lane;
        Hout[rb + e] = (v[i] - mean) * rs * G[e] + Bv[e];
    }
}

// ---------------- final tiny projection: [B,64] @ out_w[5,64]^T + out_b ----------------
__global__ __launch_bounds__(256) void out_kernel(
    const float* __restrict__ Z, const float* __restrict__ OW,
    const float* __restrict__ OB, float* __restrict__ OUT)
{
    const int b = blockIdx.x * blockDim.x + threadIdx.x;
    if (b >= cB) return;
    float acc[cC];
#pragma unroll
    for (int c = 0; c < cC; c++) acc[c] = OB[c];
    const float* zr = Z + (size_t)b * 64;
    for (int k = 0; k < 64; k++) {
        const float z = zr[k];
#pragma unroll
        for (int c = 0; c < cC; c++) acc[c] = fmaf(z, OW[c * 64 + k], acc[c]);
    }
#pragma unroll
    for (int c = 0; c < cC; c++) OUT[(size_t)b * cC + c] = acc[c];
}

// ---------------- launch ----------------
static float* symaddr(const void* sym) {
    void* p = nullptr;
    cudaGetSymbolAddress(&p, sym);
    return (float*)p;
}

extern "C" void kernel_launch(void* const* d_in, const int* in_sizes, int n_in,
                              void* d_out, int out_size)
{
    const float* x       = (const float*)d_in[0];
    const int*   st      = (const int*)  d_in[1];
    const float* gps_w   = (const float*)d_in[2];
    const float* gps_b   = (const float*)d_in[3];
    const float* ang_w   = (const float*)d_in[4];
    const float* ang_b   = (const float*)d_in[5];
    const float* qkv_w   = (const float*)d_in[6];
    const float* qkv_b   = (const float*)d_in[7];
    const float* attn_ow = (const float*)d_in[8];
    const float* attn_ob = (const float*)d_in[9];
    const float* ln1_g   = (const float*)d_in[10];
    const float* ln1_b   = (const float*)d_in[11];
    const float* ff1_w   = (const float*)d_in[12];
    const float* ff1_b   = (const float*)d_in[13];
    const float* ff2_w   = (const float*)d_in[14];
    const float* ff2_b   = (const float*)d_in[15];
    const float* ln2_g   = (const float*)d_in[16];
    const float* ln2_b   = (const float*)d_in[17];
    const float* fc1_w   = (const float*)d_in[18];
    const float* fc1_b   = (const float*)d_in[19];
    const float* fc2_w   = (const float*)d_in[20];
    const float* fc2_b   = (const float*)d_in[21];
    const float* out_w   = (const float*)d_in[22];
    const float* out_b   = (const float*)d_in[23];
    float* out = (float*)d_out;

    float* H  = symaddr(g_H);
    float* T  = symaddr(g_T);
    float* O  = symaddr(g_O);
    float* Cb = symaddr(g_Cb);
    float* Z1 = symaddr(g_Z1);
    float* Z2 = symaddr(g_Z2);

    const int MB = cBS / 64;   // 2560 row tiles

    // 1. dual-expert embed -> H [BS,256]
    embed_kernel<<<dim3(cE / 64, MB), 256>>>(x, gps_w, gps_b, ang_w, ang_b, st, H);

    // 2. transformer layers
    for (int l = 0; l < cL; l++) {
        const float* qw = qkv_w   + (size_t)l * 3 * cE * cE;
        const float* qb = qkv_b   + (size_t)l * 3 * cE;
        const float* ow = attn_ow + (size_t)l * cE * cE;
        const float* ob = attn_ob + (size_t)l * cE;
        const float* f1w = ff1_w  + (size_t)l * cF * cE;
        const float* f1b = ff1_b  + (size_t)l * cF;
        const float* f2w = ff2_w  + (size_t)l * cE * cF;
        const float* f2b = ff2_b  + (size_t)l * cE;

        // QKV: [BS,256] x [768,256]^T -> T[BS,768]
        gemm_bias<false><<<dim3(768 / 64, MB), 256>>>(H, qw, qb, T, cBS, 768, cE);
        // attention -> O[BS,256]
        attn_kernel<<<(cB * cNH * 32) / 256, 256>>>(T, O);
        // out proj: O x [256,256]^T -> Cb
        gemm_bias<false><<<dim3(cE / 64, MB), 256>>>(O, ow, ob, Cb, cBS, cE, cE);
        // H = LN(H + Cb)
        add_ln_kernel<<<cBS / 8, 256>>>(H, Cb, ln1_g + l * cE, ln1_b + l * cE, H);
        // FF1: relu(H x [2048,256]^T) -> T[BS,2048]
        gemm_bias<true><<<dim3(cF / 64, MB), 256>>>(H, f1w, f1b, T, cBS, cF, cE);
        // FF2: T x [256,2048]^T -> Cb
        gemm_bias<false><<<dim3(cE / 64, MB), 256>>>(T, f2w, f2b, Cb, cBS, cE, cF);
        // H = LN(H + Cb)
        add_ln_kernel<<<cBS / 8, 256>>>(H, Cb, ln2_g + l * cE, ln2_b + l * cE, H);
    }

    // 3. head: H viewed as [B,1280]
    gemm_bias<false><<<dim3(128 / 64, cB / 64), 256>>>(H, fc1_w, fc1_b, Z1, cB, 128, cZK);
    gemm_bias<false><<<dim3(1, cB / 64), 256>>>(Z1, fc2_w, fc2_b, Z2, cB, 64, 128);
    out_kernel<<<cB / 256, 256>>>(Z2, out_w, out_b, out);
}

// round 3
// speedup vs baseline: 2.5791x; 2.5791x over previous
#include <cuda_runtime.h>
#include <cuda_bf16.h>
#include <cstdint>

// ---------------- problem constants ----------------
constexpr int cB = 32768, cS = 5, cD = 512, cE = 256, cNH = 4,
              cF = 2048, cL = 2, cC = 5;
constexpr int cBS = cB * cS;               // 163840 rows
constexpr int cZK = cS * cE;               // 1280, head input dim

// ---------------- scratch (device globals; no allocs) ----------------
__device__ float g_H [(size_t)cBS * cE];   // hidden state [BS,256]
__device__ float g_T [(size_t)cBS * cF];   // qkv [BS,768] / ff1 [BS,2048] / expert G
__device__ float g_O [(size_t)cBS * cE];   // attention output
__device__ float g_Cb[(size_t)cBS * cE];   // pre-LN gemm output / expert A
__device__ float g_Z1[(size_t)cB * 128];
__device__ float g_Z2[(size_t)cB * 64];

// =================== helpers ===================
__device__ __forceinline__ uint32_t smem_u32(const void* p) {
    uint32_t a;
    asm("{ .reg .u64 t; cvta.to.shared.u64 t, %1; cvt.u32.u64 %0, t; }"
        : "=r"(a) : "l"(p));
    return a;
}
__device__ __forceinline__ void ldsm4(uint32_t& r0, uint32_t& r1,
                                      uint32_t& r2, uint32_t& r3, uint32_t addr) {
    asm volatile("ldmatrix.sync.aligned.m8n8.x4.shared.b16 {%0,%1,%2,%3}, [%4];"
                 : "=r"(r0), "=r"(r1), "=r"(r2), "=r"(r3) : "r"(addr));
}
__device__ __forceinline__ void mma16816(float* d, const uint32_t* a,
                                         uint32_t b0, uint32_t b1) {
    asm volatile(
        "mma.sync.aligned.m16n8k16.row.col.f32.bf16.bf16.f32 "
        "{%0,%1,%2,%3}, {%4,%5,%6,%7}, {%8,%9}, {%0,%1,%2,%3};"
        : "+f"(d[0]), "+f"(d[1]), "+f"(d[2]), "+f"(d[3])
        : "r"(a[0]), "r"(a[1]), "r"(a[2]), "r"(a[3]), "r"(b0), "r"(b1));
}
// split a float4 into bf16-hi (packed 2x bf162) and bf16-lo
__device__ __forceinline__ void split4(float4 v, uint2& hi, uint2& lo) {
    __nv_bfloat162 h0 = __float22bfloat162_rn(make_float2(v.x, v.y));
    __nv_bfloat162 h1 = __float22bfloat162_rn(make_float2(v.z, v.w));
    float2 f0 = __bfloat1622float2(h0), f1 = __bfloat1622float2(h1);
    __nv_bfloat162 l0 = __float22bfloat162_rn(make_float2(v.x - f0.x, v.y - f0.y));
    __nv_bfloat162 l1 = __float22bfloat162_rn(make_float2(v.z - f1.x, v.w - f1.y));
    hi = make_uint2(*(uint32_t*)&h0, *(uint32_t*)&h1);
    lo = make_uint2(*(uint32_t*)&l0, *(uint32_t*)&l1);
}

// =================== tensor-core GEMM (mma.sync bf16, 3-term split) ===================
// C[m,n] = A[m,:] . W[n,:] + bias[n], optional ReLU.
// CTA tile 128x128, BK=32; 8 warps, each 64x32.
// Requires M%128==0, N%128==0, K%32==0.
constexpr int SROW = 80;                   // smem row stride bytes (16B-aligned, conflict-free)
constexpr int SBUF = 128 * SROW;           // 10240 B per operand buffer
constexpr int GEMM_SMEM = 4 * SBUF;        // Ah, Al, Wh, Wl

template<bool RELU>
__global__ __launch_bounds__(256) void gemm_mma(
    const float* __restrict__ A, const float* __restrict__ W,
    const float* __restrict__ bias, float* __restrict__ C,
    int M, int N, int K)
{
    extern __shared__ char sm[];
    const uint32_t sAh = smem_u32(sm);
    const uint32_t sAl = sAh + SBUF;
    const uint32_t sWh = sAh + 2 * SBUF;
    const uint32_t sWl = sAh + 3 * SBUF;

    const int tid = threadIdx.x;
    const int wid = tid >> 5, lane = tid & 31;
    const int bm = blockIdx.y * 128, bn = blockIdx.x * 128;
    const int wm = (wid & 1) * 64, wn = (wid >> 1) * 32;

    float acc[4][4][4];
#pragma unroll
    for (int i = 0; i < 4; i++)
#pragma unroll
        for (int j = 0; j < 4; j++)
#pragma unroll
            for (int r = 0; r < 4; r++) acc[i][j][r] = 0.f;

    // loader mapping: thread -> row tid/2 (0..127), 16 floats at col (tid&1)*16
    const int lrow = tid >> 1;
    const int lcolf = (tid & 1) * 16;
    const float* Ag = A + (size_t)(bm + lrow) * K + lcolf;
    const float* Wg = W + (size_t)(bn + lrow) * K + lcolf;
    const uint32_t sts_base = (uint32_t)(lrow * SROW + lcolf * 2);

    // ldmatrix addresses (constant across chunks)
    const int arow = wm + (lane & 15);
    const uint32_t a_off = (uint32_t)(arow * SROW + (lane >> 4) * 16);
    const int wrow0 = wn + (lane & 7) + ((lane >> 4) & 1) * 8;
    const uint32_t w_off0 = (uint32_t)(wrow0 * SROW + ((lane >> 3) & 1) * 16);

    const int nk = K / 32;

    float4 pa[4], pw[4];
#pragma unroll
    for (int j = 0; j < 4; j++) {
        pa[j] = *(const float4*)(Ag + 4 * j);
        pw[j] = *(const float4*)(Wg + 4 * j);
    }

    for (int c = 0; c < nk; ++c) {
        // stage current chunk (convert fp32 -> bf16 hi/lo)
#pragma unroll
        for (int j = 0; j < 4; j++) {
            uint2 hi, lo;
            const uint32_t so = sts_base + j * 8;
            split4(pa[j], hi, lo);
            *(uint2*)(sm + (so))          = hi;
            *(uint2*)(sm + (SBUF + so))   = lo;
            split4(pw[j], hi, lo);
            *(uint2*)(sm + (2*SBUF + so)) = hi;
            *(uint2*)(sm + (3*SBUF + so)) = lo;
        }
        __syncthreads();

        // prefetch next chunk
        if (c + 1 < nk) {
            const size_t o = (size_t)(c + 1) * 32;
#pragma unroll
            for (int j = 0; j < 4; j++) {
                pa[j] = *(const float4*)(Ag + o + 4 * j);
                pw[j] = *(const float4*)(Wg + o + 4 * j);
            }
        }

#pragma unroll
        for (int ks = 0; ks < 2; ++ks) {
            const uint32_t ko = ks * 32;
            uint32_t aF[4][4], bF[4][2];
            // Ah fragments
#pragma unroll
            for (int mf = 0; mf < 4; mf++)
                ldsm4(aF[mf][0], aF[mf][1], aF[mf][2], aF[mf][3],
                      sAh + a_off + mf * (16 * SROW) + ko);
            // Wh fragments
#pragma unroll
            for (int p = 0; p < 2; p++) {
                uint32_t r0, r1, r2, r3;
                ldsm4(r0, r1, r2, r3, sWh + w_off0 + p * (16 * SROW) + ko);
                bF[2*p][0] = r0; bF[2*p][1] = r1;
                bF[2*p+1][0] = r2; bF[2*p+1][1] = r3;
            }
            // pass 1: Ah * Wh
#pragma unroll
            for (int mf = 0; mf < 4; mf++)
#pragma unroll
                for (int nf = 0; nf < 4; nf++)
                    mma16816(acc[mf][nf], aF[mf], bF[nf][0], bF[nf][1]);
            // pass 2: Ah * Wl
            {
                uint32_t cF[4][2];
#pragma unroll
                for (int p = 0; p < 2; p++) {
                    uint32_t r0, r1, r2, r3;
                    ldsm4(r0, r1, r2, r3, sWl + w_off0 + p * (16 * SROW) + ko);
                    cF[2*p][0] = r0; cF[2*p][1] = r1;
                    cF[2*p+1][0] = r2; cF[2*p+1][1] = r3;
                }
#pragma unroll
                for (int mf = 0; mf < 4; mf++)
#pragma unroll
                    for (int nf = 0; nf < 4; nf++)
                        mma16816(acc[mf][nf], aF[mf], cF[nf][0], cF[nf][1]);
            }
            // pass 3: Al * Wh
            {
                uint32_t eF[4][4];
#pragma unroll
                for (int mf = 0; mf < 4; mf++)
                    ldsm4(eF[mf][0], eF[mf][1], eF[mf][2], eF[mf][3],
                          sAl + a_off + mf * (16 * SROW) + ko);
#pragma unroll
                for (int mf = 0; mf < 4; mf++)
#pragma unroll
                    for (int nf = 0; nf < 4; nf++)
                        mma16816(acc[mf][nf], eF[mf], bF[nf][0], bF[nf][1]);
            }
        }
        __syncthreads();
    }

    // epilogue: bias + optional relu, direct STG
    const int erow = (lane >> 2);
    const int ecol = (lane & 3) * 2;
#pragma unroll
    for (int nf = 0; nf < 4; nf++) {
        const int col = bn + wn + nf * 8 + ecol;
        const float2 bv = *(const float2*)&bias[col];
#pragma unroll
        for (int mf = 0; mf < 4; mf++) {
            const int r0 = bm + wm + mf * 16 + erow;
            float2 o0, o1;
            o0.x = acc[mf][nf][0] + bv.x; o0.y = acc[mf][nf][1] + bv.y;
            o1.x = acc[mf][nf][2] + bv.x; o1.y = acc[mf][nf][3] + bv.y;
            if (RELU) {
                o0.x = fmaxf(o0.x, 0.f); o0.y = fmaxf(o0.y, 0.f);
                o1.x = fmaxf(o1.x, 0.f); o1.y = fmaxf(o1.y, 0.f);
            }
            *(float2*)&C[(size_t)r0 * N + col] = o0;
            *(float2*)&C[(size_t)(r0 + 8) * N + col] = o1;
        }
    }
}

// =================== small SIMT GEMM (head fc2) ===================
template<bool RELU>
__global__ __launch_bounds__(256) void gemm_bias(
    const float* __restrict__ A, const float* __restrict__ W,
    const float* __restrict__ bias, float* __restrict__ C,
    int M, int N, int K)
{
    __shared__ float As[16][68];
    __shared__ float Ws[16][68];
    const int t  = threadIdx.x;
    const int bm = blockIdx.y * 64, bn = blockIdx.x * 64;
    const int tm = (t >> 4) << 2;
    const int tn = (t & 15) << 2;
    const int lr = t >> 2;
    const int lc = (t & 3) << 2;

    float acc[4][4] = {};
    const float* Ap = A + (size_t)(bm + lr) * K + lc;
    const float* Wp = W + (size_t)(bn + lr) * K + lc;

    for (int k0 = 0; k0 < K; k0 += 16) {
        float4 av = *(const float4*)(Ap + k0);
        float4 wv = (bn + lr < N) ? *(const float4*)(Wp + k0) : make_float4(0, 0, 0, 0);
        As[lc+0][lr]=av.x; As[lc+1][lr]=av.y; As[lc+2][lr]=av.z; As[lc+3][lr]=av.w;
        Ws[lc+0][lr]=wv.x; Ws[lc+1][lr]=wv.y; Ws[lc+2][lr]=wv.z; Ws[lc+3][lr]=wv.w;
        __syncthreads();
#pragma unroll
        for (int k = 0; k < 16; k++) {
            float4 a4 = *(const float4*)&As[k][tm];
            float4 w4 = *(const float4*)&Ws[k][tn];
            const float ar[4] = {a4.x, a4.y, a4.z, a4.w};
            const float wr[4] = {w4.x, w4.y, w4.z, w4.w};
#pragma unroll
            for (int r = 0; r < 4; r++)
#pragma unroll
                for (int c = 0; c < 4; c++)
                    acc[r][c] = fmaf(ar[r], wr[c], acc[r][c]);
        }
        __syncthreads();
    }
    if (bn + tn >= N) return;
    float4 bv = *(const float4*)&bias[bn + tn];
    const float bb[4] = {bv.x, bv.y, bv.z, bv.w};
#pragma unroll
    for (int r = 0; r < 4; r++) {
        float4 o; float* op = (float*)&o;
#pragma unroll
        for (int c = 0; c < 4; c++) {
            float v = acc[r][c] + bb[c];
            if (RELU) v = fmaxf(v, 0.f);
            op[c] = v;
        }
        *(float4*)&C[(size_t)(bm + tm + r) * N + bn + tn] = o;
    }
}

// =================== expert select ===================
__global__ __launch_bounds__(256) void select_kernel(
    const float* __restrict__ G, const float* __restrict__ A2,
    const int* __restrict__ ST, float* __restrict__ H)
{
    const size_t i = (size_t)blockIdx.x * blockDim.x + threadIdx.x;  // float4 idx
    const int row = (int)(i >> 6);                                   // 64 float4s per row
    const float4 v = (ST[row] == 0) ? ((const float4*)G)[i] : ((const float4*)A2)[i];
    ((float4*)H)[i] = v;
}

// =================== attention: one warp per (batch, head) ===================
__global__ __launch_bounds__(256) void attn_kernel(
    const float* __restrict__ QKV, float* __restrict__ O)
{
    const int gwarp = (blockIdx.x * blockDim.x + threadIdx.x) >> 5;
    const int lane  = threadIdx.x & 31;
    if (gwarp >= cB * cNH) return;
    const int b = gwarp >> 2, h = gwarp & 3;

    const float* base = QKV + (size_t)b * cS * 768 + h * 64 + 2 * lane;
    float q[cS][2], kk[cS][2], vv[cS][2];
#pragma unroll
    for (int s = 0; s < cS; s++) {
        const float* r = base + s * 768;
        float2 qv = *(const float2*)(r);
        float2 kv = *(const float2*)(r + 256);
        float2 vw = *(const float2*)(r + 512);
        q [s][0] = qv.x; q [s][1] = qv.y;
        kk[s][0] = kv.x; kk[s][1] = kv.y;
        vv[s][0] = vw.x; vv[s][1] = vw.y;
    }
    float sc[cS][cS];
#pragma unroll
    for (int i = 0; i < cS; i++)
#pragma unroll
        for (int j = 0; j < cS; j++) {
            float p = q[i][0] * kk[j][0] + q[i][1] * kk[j][1];
#pragma unroll
            for (int o = 16; o > 0; o >>= 1) p += __shfl_xor_sync(0xFFFFFFFFu, p, o);
            sc[i][j] = p * 0.125f;
        }
#pragma unroll
    for (int i = 0; i < cS; i++) {
        float m = sc[i][0];
#pragma unroll
        for (int j = 1; j < cS; j++) m = fmaxf(m, sc[i][j]);
        float e[cS], s = 0.f;
#pragma unroll
        for (int j = 0; j < cS; j++) { e[j] = expf(sc[i][j] - m); s += e[j]; }
        const float inv = 1.f / s;
        float o0 = 0.f, o1 = 0.f;
#pragma unroll
        for (int j = 0; j < cS; j++) {
            const float a = e[j] * inv;
            o0 = fmaf(a, vv[j][0], o0);
            o1 = fmaf(a, vv[j][1], o1);
        }
        float2 ov = {o0, o1};
        *(float2*)&O[(size_t)(b * cS + i) * cE + h * 64 + 2 * lane] = ov;
    }
}

// =================== fused residual + layernorm ===================
__global__ __launch_bounds__(256) void add_ln_kernel(
    const float* __restrict__ Hin, const float* __restrict__ Cin,
    const float* __restrict__ G, const float* __restrict__ Bv,
    float* __restrict__ Hout)
{
    const int row  = blockIdx.x * 8 + (threadIdx.x >> 5);
    const int lane = threadIdx.x & 31;
    const size_t rb = (size_t)row * cE;

    float v[8];
    float s = 0.f;
#pragma unroll
    for (int i = 0; i < 8; i++) {
        const int e = i * 32 + lane;
        v[i] = Hin[rb + e] + Cin[rb + e];
        s += v[i];
    }
#pragma unroll
    for (int o = 16; o > 0; o >>= 1) s += __shfl_xor_sync(0xFFFFFFFFu, s, o);
    const float mean = s * (1.f / cE);

    float vs = 0.f;
#pragma unroll
    for (int i = 0; i < 8; i++) { const float d = v[i] - mean; vs += d * d; }
#pragma unroll
    for (int o = 16; o > 0; o >>= 1) vs += __shfl_xor_sync(0xFFFFFFFFu, vs, o);
    const float rs = rsqrtf(vs * (1.f / cE) + 1e-5f);

#pragma unroll
    for (int i = 0; i < 8; i++) {
        const int e = i * 32 + lane;
        Hout[rb + e] = (v[i] - mean) * rs * G[e] + Bv[e];
    }
}

// =================== final tiny projection ===================
__global__ __launch_bounds__(256) void out_kernel(
    const float* __restrict__ Z, const float* __restrict__ OW,
    const float* __restrict__ OB, float* __restrict__ OUT)
{
    const int b = blockIdx.x * blockDim.x + threadIdx.x;
    if (b >= cB) return;
    float acc[cC];
#pragma unroll
    for (int c = 0; c < cC; c++) acc[c] = OB[c];
    const float* zr = Z + (size_t)b * 64;
    for (int k = 0; k < 64; k++) {
        const float z = zr[k];
#pragma unroll
        for (int c = 0; c < cC; c++) acc[c] = fmaf(z, OW[c * 64 + k], acc[c]);
    }
#pragma unroll
    for (int c = 0; c < cC; c++) OUT[(size_t)b * cC + c] = acc[c];
}

// ---------------- launch ----------------
static float* symaddr(const void* sym) {
    void* p = nullptr;
    cudaGetSymbolAddress(&p, sym);
    return (float*)p;
}

extern "C" void kernel_launch(void* const* d_in, const int* in_sizes, int n_in,
                              void* d_out, int out_size)
{
    const float* x       = (const float*)d_in[0];
    const int*   st      = (const int*)  d_in[1];
    const float* gps_w   = (const float*)d_in[2];
    const float* gps_b   = (const float*)d_in[3];
    const float* ang_w   = (const float*)d_in[4];
    const float* ang_b   = (const float*)d_in[5];
    const float* qkv_w   = (const float*)d_in[6];
    const float* qkv_b   = (const float*)d_in[7];
    const float* attn_ow = (const float*)d_in[8];
    const float* attn_ob = (const float*)d_in[9];
    const float* ln1_g   = (const float*)d_in[10];
    const float* ln1_b   = (const float*)d_in[11];
    const float* ff1_w   = (const float*)d_in[12];
    const float* ff1_b   = (const float*)d_in[13];
    const float* ff2_w   = (const float*)d_in[14];
    const float* ff2_b   = (const float*)d_in[15];
    const float* ln2_g   = (const float*)d_in[16];
    const float* ln2_b   = (const float*)d_in[17];
    const float* fc1_w   = (const float*)d_in[18];
    const float* fc1_b   = (const float*)d_in[19];
    const float* fc2_w   = (const float*)d_in[20];
    const float* fc2_b   = (const float*)d_in[21];
    const float* out_w   = (const float*)d_in[22];
    const float* out_b   = (const float*)d_in[23];
    float* out = (float*)d_out;

    float* H  = symaddr(g_H);
    float* T  = symaddr(g_T);
    float* O  = symaddr(g_O);
    float* Cb = symaddr(g_Cb);
    float* Z1 = symaddr(g_Z1);
    float* Z2 = symaddr(g_Z2);

    const int MT = cBS / 128;   // 1280 row tiles

    // 1. dual-expert embed: both experts via tensor GEMM, then per-row select
    gemm_mma<true><<<dim3(cE / 128, MT), 256, GEMM_SMEM>>>(x, gps_w, gps_b, T,  cBS, cE, cD);
    gemm_mma<true><<<dim3(cE / 128, MT), 256, GEMM_SMEM>>>(x, ang_w, ang_b, Cb, cBS, cE, cD);
    select_kernel<<<(cBS * cE / 4) / 256, 256>>>(T, Cb, st, H);

    // 2. transformer layers
    for (int l = 0; l < cL; l++) {
        const float* qw  = qkv_w   + (size_t)l * 3 * cE * cE;
        const float* qb  = qkv_b   + (size_t)l * 3 * cE;
        const float* ow  = attn_ow + (size_t)l * cE * cE;
        const float* ob  = attn_ob + (size_t)l * cE;
        const float* f1w = ff1_w   + (size_t)l * cF * cE;
        const float* f1b = ff1_b   + (size_t)l * cF;
        const float* f2w = ff2_w   + (size_t)l * cE * cF;
        const float* f2b = ff2_b   + (size_t)l * cE;

        gemm_mma<false><<<dim3(768 / 128, MT), 256, GEMM_SMEM>>>(H, qw, qb, T, cBS, 768, cE);
        attn_kernel<<<(cB * cNH * 32) / 256, 256>>>(T, O);
        gemm_mma<false><<<dim3(cE / 128, MT), 256, GEMM_SMEM>>>(O, ow, ob, Cb, cBS, cE, cE);
        add_ln_kernel<<<cBS / 8, 256>>>(H, Cb, ln1_g + l * cE, ln1_b + l * cE, H);
        gemm_mma<true><<<dim3(cF / 128, MT), 256, GEMM_SMEM>>>(H, f1w, f1b, T, cBS, cF, cE);
        gemm_mma<false><<<dim3(cE / 128, MT), 256, GEMM_SMEM>>>(T, f2w, f2b, Cb, cBS, cE, cF);
        add_ln_kernel<<<cBS / 8, 256>>>(H, Cb, ln2_g + l * cE, ln2_b + l * cE, H);
    }

    // 3. head: H viewed as [B,1280]
    gemm_mma<false><<<dim3(1, cB / 128), 256, GEMM_SMEM>>>(H, fc1_w, fc1_b, Z1, cB, 128, cZK);
    gemm_bias<false><<<dim3(1, cB / 64), 256>>>(Z1, fc2_w, fc2_b, Z2, cB, 64, 128);
    out_kernel<<<cB / 256, 256>>>(Z2, out_w, out_b, out);
}